// round 7
// baseline (speedup 1.0000x reference)
#include <cuda_runtime.h>
#include <math.h>
#include <stdint.h>

// ---------------- problem constants ----------------
#define NROWS   32768          // 32 * 32 * 32  (B * H * W)
#define DDIM    256            // channels / code dim
#define KCODES  1024           // codebook size
#define Q_ELEMS 8388608        // 32*256*32*32
#define ENC_ELEMS 33554432     // 32768 * 1024

// output layout: [loss(1) | quantized_st(Q_ELEMS) | perplexity(1) | encodings(ENC_ELEMS)]
#define Q_OFF    1
#define PERP_OFF (1 + Q_ELEMS)
#define ENC_OFF  (2 + Q_ELEMS)

// GEMM tiling
#define BM 128
#define BN 128
#define BK 32

// ---------------- scratch (device globals: no allocation allowed) ----------------
__device__ float              g_eT[DDIM * KCODES];   // embedding transposed [d][k]
__device__ float              g_enorm[KCODES];       // ||e_k||^2
__device__ unsigned long long g_rowmin[NROWS];       // packed (score|code) per row
__device__ int                g_idx[NROWS];          // argmin index per row
__device__ int                g_counts[KCODES];      // histogram
__device__ double             g_loss;                // sum of squared diffs

// ---------------- packed f32x2 helpers ----------------
__device__ __forceinline__ unsigned long long dup2(float v) {
    unsigned long long r;
    asm("mov.b64 %0, {%1, %1};" : "=l"(r) : "r"(__float_as_uint(v)));
    return r;
}
__device__ __forceinline__ void unpack2(unsigned long long p, float& lo, float& hi) {
    unsigned int a, b;
    asm("mov.b64 {%0, %1}, %2;" : "=r"(a), "=r"(b) : "l"(p));
    lo = __uint_as_float(a);
    hi = __uint_as_float(b);
}
__device__ __forceinline__ void fma2(unsigned long long& acc,
                                     unsigned long long a, unsigned long long b) {
    asm("fma.rn.f32x2 %0, %1, %2, %0;" : "+l"(acc) : "l"(a), "l"(b));
}

// ---------------- init: zero accumulators ----------------
__global__ void init_kernel() {
    int t = threadIdx.x;
    if (t < KCODES) g_counts[t] = 0;
    if (t == 0) g_loss = 0.0;
}

// ---------------- prep: transpose embedding + norms (exact fp32) ----------------
__global__ void prep_kernel(const float* __restrict__ emb) {
    int k = blockIdx.x;
    int d = threadIdx.x;
    float v = emb[k * DDIM + d];
    g_eT[d * KCODES + k] = v;
    __shared__ float red[DDIM];
    red[d] = v * v;
    __syncthreads();
    for (int s = 128; s > 0; s >>= 1) {
        if (d < s) red[d] += red[d + s];
        __syncthreads();
    }
    if (d == 0) g_enorm[k] = red[0];
}

// ---------------- argmin key packing (ties -> lowest index, like jnp.argmin) ----------------
__device__ __forceinline__ unsigned long long pack_key(float s, int code) {
    unsigned int u = __float_as_uint(s);
    u = (u & 0x80000000u) ? ~u : (u | 0x80000000u);
    return (((unsigned long long)u) << 32) | (unsigned int)code;
}

// ---------------- cp.async tile loader ----------------
__device__ __forceinline__ void issue_tiles(float* As, float* Bs,
                                            const float* xbase, const float* ebase,
                                            int kk, int tid) {
    #pragma unroll
    for (int i = 0; i < 4; i++) {
        int t  = tid + i * 256;              // 0..1023 float4 slots
        int k  = t >> 5;
        int m4 = t & 31;
        const float* src = xbase + (size_t)(kk + k) * 1024 + m4 * 4;
        unsigned int dst = (unsigned int)__cvta_generic_to_shared(As + k * BM + m4 * 4);
        asm volatile("cp.async.cg.shared.global [%0], [%1], 16;" :: "r"(dst), "l"(src));
    }
    #pragma unroll
    for (int i = 0; i < 4; i++) {
        int t  = tid + i * 256;
        int k  = t >> 5;
        int n4 = t & 31;
        const float* src = ebase + (size_t)(kk + k) * KCODES + n4 * 4;
        unsigned int dst = (unsigned int)__cvta_generic_to_shared(Bs + k * BN + n4 * 4);
        asm volatile("cp.async.cg.shared.global [%0], [%1], 16;" :: "r"(dst), "l"(src));
    }
    asm volatile("cp.async.commit_group;");
}

// ---------------- main: fused fp32 GEMM (FFMA2) + argmin ----------------
// grid = 2048 blocks: rowTile = bx>>3 (128 rows), codeTile = bx&7 (128 codes, fast idx
// so the 8 blocks sharing an A tile run concurrently and hit L2).
// score_k = ||e_k||^2 - 2 * x.e_k  (||x||^2 per-row constant -> argmin-invariant)
__global__ __launch_bounds__(256, 2)
void argmin_kernel(const float* __restrict__ x,
                   const float* __restrict__ enorm,
                   unsigned long long* __restrict__ rowmin) {
    extern __shared__ float sm[];
    float* As0 = sm;                    // [BK][BM]
    float* As1 = sm + BK * BM;
    float* Bs0 = sm + 2 * BK * BM;      // [BK][BN]
    float* Bs1 = sm + 2 * BK * BM + BK * BN;

    const int tid = threadIdx.x;
    const int bx  = blockIdx.x;
    const int rowTile = bx >> 3;
    const int ct      = bx & 7;
    const int m0  = rowTile * BM;       // global row base (128 rows, same batch b)
    const int b   = m0 >> 10;
    const int hw0 = m0 & 1023;
    const float* xbase = x + (size_t)b * (DDIM * 1024) + hw0;
    const float* ebase = g_eT + ct * BN;

    const int tx = tid & 15;            // 8-code group
    const int ty = tid >> 4;            // 8-row group

    issue_tiles(As0, Bs0, xbase, ebase, 0, tid);

    unsigned long long acc[4][8];       // [row-pair][code] packed fp32x2
    #pragma unroll
    for (int i = 0; i < 4; i++)
        #pragma unroll
        for (int j = 0; j < 8; j++) acc[i][j] = 0ULL;

    for (int c = 0; c < 8; c++) {
        const float* Ab = (c & 1) ? As1 : As0;
        const float* Bb = (c & 1) ? Bs1 : Bs0;
        if (c < 7) {
            issue_tiles(((c + 1) & 1) ? As1 : As0, ((c + 1) & 1) ? Bs1 : Bs0,
                        xbase, ebase, (c + 1) * BK, tid);
            asm volatile("cp.async.wait_group 1;");
        } else {
            asm volatile("cp.async.wait_group 0;");
        }
        __syncthreads();

        #pragma unroll 8
        for (int k = 0; k < BK; k++) {
            unsigned long long aP[4];
            #pragma unroll
            for (int i = 0; i < 4; i++)
                aP[i] = *reinterpret_cast<const unsigned long long*>(
                    Ab + k * BM + ty * 8 + i * 2);
            float4 b0 = *reinterpret_cast<const float4*>(Bb + k * BN + tx * 8);
            float4 b1 = *reinterpret_cast<const float4*>(Bb + k * BN + tx * 8 + 4);
            unsigned long long bd[8];
            bd[0] = dup2(b0.x); bd[1] = dup2(b0.y); bd[2] = dup2(b0.z); bd[3] = dup2(b0.w);
            bd[4] = dup2(b1.x); bd[5] = dup2(b1.y); bd[6] = dup2(b1.z); bd[7] = dup2(b1.w);
            #pragma unroll
            for (int i = 0; i < 4; i++)
                #pragma unroll
                for (int j = 0; j < 8; j++)
                    fma2(acc[i][j], aP[i], bd[j]);
        }
        __syncthreads();
    }

    // ---- epilogue: score -> per-row argmin over this block's 128 codes ----
    const int codeBase = ct * BN + tx * 8;
    float en[8];
    #pragma unroll
    for (int j = 0; j < 8; j++) en[j] = enorm[codeBase + j];

    #pragma unroll
    for (int i = 0; i < 4; i++) {
        unsigned long long bestLo = 0xFFFFFFFFFFFFFFFFull;
        unsigned long long bestHi = 0xFFFFFFFFFFFFFFFFull;
        #pragma unroll
        for (int j = 0; j < 8; j++) {
            float dLo, dHi;
            unpack2(acc[i][j], dLo, dHi);
            unsigned long long kLo = pack_key(en[j] - 2.0f * dLo, codeBase + j);
            unsigned long long kHi = pack_key(en[j] - 2.0f * dHi, codeBase + j);
            bestLo = (kLo < bestLo) ? kLo : bestLo;
            bestHi = (kHi < bestHi) ? kHi : bestHi;
        }
        // reduce across the 16 tx lanes (same half-warp: lane = ty%2*16 + tx)
        #pragma unroll
        for (int off = 1; off < 16; off <<= 1) {
            unsigned long long o = __shfl_xor_sync(0xFFFFFFFFu, bestLo, off);
            bestLo = (o < bestLo) ? o : bestLo;
            o = __shfl_xor_sync(0xFFFFFFFFu, bestHi, off);
            bestHi = (o < bestHi) ? o : bestHi;
        }
        if (tx == 0) {
            int r0 = m0 + ty * 8 + i * 2;
            atomicMin(rowmin + r0,     bestLo);   // no return use -> REDG.MIN
            atomicMin(rowmin + r0 + 1, bestHi);
        }
    }
}

// ---------------- extract argmin index from packed keys ----------------
__global__ void extract_kernel(const unsigned long long* __restrict__ rm,
                               int* __restrict__ idx) {
    int n = blockIdx.x * 256 + threadIdx.x;
    if (n < NROWS) idx[n] = (int)(rm[n] & 0xFFFFFFFFu);
}

// ---------------- gather quantized + commitment-loss accumulation ----------------
// outq = d_out + 1 is only 4B aligned -> scalar stores.
__global__ void gather_loss_kernel(const float* __restrict__ x,
                                   const float* __restrict__ emb,
                                   const int* __restrict__ idx,
                                   float* __restrict__ outq) {
    const int t = blockIdx.x * blockDim.x + threadIdx.x;
    double local = 0.0;
    for (int v = t; v < Q_ELEMS / 4; v += 524288) {
        int i  = v * 4;
        int hw = i & 1023;
        int c  = (i >> 10) & 255;
        int b  = i >> 18;
        int n0 = (b << 10) | hw;
        float4 xv = *reinterpret_cast<const float4*>(x + i);
        int id0 = idx[n0], id1 = idx[n0 + 1], id2 = idx[n0 + 2], id3 = idx[n0 + 3];
        float q0 = emb[id0 * DDIM + c];
        float q1 = emb[id1 * DDIM + c];
        float q2 = emb[id2 * DDIM + c];
        float q3 = emb[id3 * DDIM + c];
        outq[i + 0] = xv.x + (q0 - xv.x);
        outq[i + 1] = xv.y + (q1 - xv.y);
        outq[i + 2] = xv.z + (q2 - xv.z);
        outq[i + 3] = xv.w + (q3 - xv.w);
        float d0 = q0 - xv.x, d1 = q1 - xv.y, d2 = q2 - xv.z, d3 = q3 - xv.w;
        local += (double)(d0 * d0 + d1 * d1) + (double)(d2 * d2 + d3 * d3);
    }
    __shared__ double red[256];
    red[threadIdx.x] = local;
    __syncthreads();
    for (int s = 128; s > 0; s >>= 1) {
        if (threadIdx.x < s) red[threadIdx.x] += red[threadIdx.x + s];
        __syncthreads();
    }
    if (threadIdx.x == 0) atomicAdd(&g_loss, red[0]);
}

// ---------------- one-hot encodings + histogram ----------------
__global__ void onehot_kernel(const int* __restrict__ idx, float* __restrict__ enc) {
    int n = blockIdx.x * blockDim.x + threadIdx.x;
    if (n < NROWS) {
        int id = idx[n];
        enc[(size_t)n * KCODES + id] = 1.0f;
        atomicAdd(&g_counts[id], 1);
    }
}

// ---------------- finalize: loss + perplexity ----------------
__global__ void finalize_kernel(float* __restrict__ out) {
    __shared__ double red[KCODES];
    int k = threadIdx.x;
    double p = (double)g_counts[k] / (double)NROWS;
    red[k] = p * log(p + 1e-10);
    __syncthreads();
    for (int s = 512; s > 0; s >>= 1) {
        if (k < s) red[k] += red[k + s];
        __syncthreads();
    }
    if (k == 0) {
        out[PERP_OFF] = (float)exp(-red[0]);
        out[0]        = (float)(0.25 * g_loss / (double)Q_ELEMS);
    }
}

// ---------------- launch ----------------
extern "C" void kernel_launch(void* const* d_in, const int* in_sizes, int n_in,
                              void* d_out, int out_size) {
    const float* x   = (const float*)d_in[0];   // [32,256,32,32]
    const float* emb = (const float*)d_in[1];   // [1024,256]
    float* out = (float*)d_out;

    static const size_t SMEM = 2 * (BK * BM + BK * BN) * sizeof(float); // 64 KB
    cudaFuncSetAttribute(argmin_kernel,
                         cudaFuncAttributeMaxDynamicSharedMemorySize, (int)SMEM);

    // resolve ALL device-global addresses via the runtime (never pass a
    // __device__ symbol directly from host code — on GB300/ATS it silently
    // dereferences the zero-filled host shadow).
    int*                d_idx;    cudaGetSymbolAddress((void**)&d_idx,    g_idx);
    float*              d_enorm;  cudaGetSymbolAddress((void**)&d_enorm,  g_enorm);
    unsigned long long* d_rowmin; cudaGetSymbolAddress((void**)&d_rowmin, g_rowmin);

    init_kernel<<<1, 1024>>>();
    prep_kernel<<<KCODES, DDIM>>>(emb);
    cudaMemsetAsync(d_rowmin, 0xFF, (size_t)NROWS * sizeof(unsigned long long));
    cudaMemsetAsync(out + ENC_OFF, 0, (size_t)ENC_ELEMS * sizeof(float));

    argmin_kernel<<<(NROWS / BM) * (KCODES / BN), 256, SMEM>>>(x, d_enorm, d_rowmin);
    extract_kernel<<<NROWS / 256, 256>>>(d_rowmin, d_idx);

    gather_loss_kernel<<<2048, 256>>>(x, emb, d_idx, out + Q_OFF);
    onehot_kernel<<<NROWS / 256, 256>>>(d_idx, out + ENC_OFF);
    finalize_kernel<<<1, KCODES>>>(out);
}

// round 8
// speedup vs baseline: 1.0002x; 1.0002x over previous
#include <cuda_runtime.h>
#include <math.h>
#include <stdint.h>

// ---------------- problem constants ----------------
#define NROWS   32768          // 32 * 32 * 32  (B * H * W)
#define DDIM    256            // channels / code dim
#define KCODES  1024           // codebook size
#define Q_ELEMS 8388608        // 32*256*32*32
#define ENC_ELEMS 33554432     // 32768 * 1024

// output layout: [loss(1) | quantized_st(Q_ELEMS) | perplexity(1) | encodings(ENC_ELEMS)]
#define Q_OFF    1
#define PERP_OFF (1 + Q_ELEMS)
#define ENC_OFF  (2 + Q_ELEMS)

// GEMM tiling
#define BM 128
#define BN 128
#define BK 32

// ---------------- scratch (device globals: no allocation allowed) ----------------
__device__ float              g_eT[DDIM * KCODES];   // embedding transposed [d][k]
__device__ float              g_enorm[KCODES];       // ||e_k||^2
__device__ unsigned long long g_rowmin[NROWS];       // packed (score|code) per row
__device__ int                g_idx[NROWS];          // argmin index per row
__device__ int                g_counts[KCODES];      // histogram
__device__ double             g_loss;                // sum of squared diffs

// ---------------- packed f32x2 helpers ----------------
__device__ __forceinline__ unsigned long long dup2(float v) {
    unsigned long long r;
    asm("mov.b64 %0, {%1, %1};" : "=l"(r) : "r"(__float_as_uint(v)));
    return r;
}
__device__ __forceinline__ void unpack2(unsigned long long p, float& lo, float& hi) {
    unsigned int a, b;
    asm("mov.b64 {%0, %1}, %2;" : "=r"(a), "=r"(b) : "l"(p));
    lo = __uint_as_float(a);
    hi = __uint_as_float(b);
}
__device__ __forceinline__ void fma2(unsigned long long& acc,
                                     unsigned long long a, unsigned long long b) {
    asm("fma.rn.f32x2 %0, %1, %2, %0;" : "+l"(acc) : "l"(a), "l"(b));
}

// ---------------- init: zero accumulators ----------------
__global__ void init_kernel() {
    int t = threadIdx.x;
    if (t < KCODES) g_counts[t] = 0;
    if (t == 0) g_loss = 0.0;
}

// ---------------- prep: transpose embedding + norms (exact fp32) ----------------
__global__ void prep_kernel(const float* __restrict__ emb) {
    int k = blockIdx.x;
    int d = threadIdx.x;
    float v = emb[k * DDIM + d];
    g_eT[d * KCODES + k] = v;
    __shared__ float red[DDIM];
    red[d] = v * v;
    __syncthreads();
    for (int s = 128; s > 0; s >>= 1) {
        if (d < s) red[d] += red[d + s];
        __syncthreads();
    }
    if (d == 0) g_enorm[k] = red[0];
}

// ---------------- argmin key packing (ties -> lowest index, like jnp.argmin) ----------------
__device__ __forceinline__ unsigned long long pack_key(float s, int code) {
    unsigned int u = __float_as_uint(s);
    u = (u & 0x80000000u) ? ~u : (u | 0x80000000u);
    return (((unsigned long long)u) << 32) | (unsigned int)code;
}

// ---------------- cp.async tile loader ----------------
__device__ __forceinline__ void issue_tiles(float* As, float* Bs,
                                            const float* xbase, const float* ebase,
                                            int kk, int tid) {
    #pragma unroll
    for (int i = 0; i < 4; i++) {
        int t  = tid + i * 256;              // 0..1023 float4 slots
        int k  = t >> 5;
        int m4 = t & 31;
        const float* src = xbase + (size_t)(kk + k) * 1024 + m4 * 4;
        unsigned int dst = (unsigned int)__cvta_generic_to_shared(As + k * BM + m4 * 4);
        asm volatile("cp.async.cg.shared.global [%0], [%1], 16;" :: "r"(dst), "l"(src));
    }
    #pragma unroll
    for (int i = 0; i < 4; i++) {
        int t  = tid + i * 256;
        int k  = t >> 5;
        int n4 = t & 31;
        const float* src = ebase + (size_t)(kk + k) * KCODES + n4 * 4;
        unsigned int dst = (unsigned int)__cvta_generic_to_shared(Bs + k * BN + n4 * 4);
        asm volatile("cp.async.cg.shared.global [%0], [%1], 16;" :: "r"(dst), "l"(src));
    }
    asm volatile("cp.async.commit_group;");
}

// ---------------- main: fused fp32 GEMM (FFMA2) + argmin ----------------
// grid = 2048 blocks: rowTile = bx>>3 (128 rows), codeTile = bx&7 (128 codes, fast idx
// so the 8 blocks sharing an A tile run concurrently and hit L2).
// score_k = ||e_k||^2 - 2 * x.e_k  (||x||^2 per-row constant -> argmin-invariant)
__global__ __launch_bounds__(256, 2)
void argmin_kernel(const float* __restrict__ x,
                   const float* __restrict__ enorm,
                   unsigned long long* __restrict__ rowmin) {
    extern __shared__ float sm[];
    float* As0 = sm;                    // [BK][BM]
    float* As1 = sm + BK * BM;
    float* Bs0 = sm + 2 * BK * BM;      // [BK][BN]
    float* Bs1 = sm + 2 * BK * BM + BK * BN;

    const int tid = threadIdx.x;
    const int bx  = blockIdx.x;
    const int rowTile = bx >> 3;
    const int ct      = bx & 7;
    const int m0  = rowTile * BM;       // global row base (128 rows, same batch b)
    const int b   = m0 >> 10;
    const int hw0 = m0 & 1023;
    const float* xbase = x + (size_t)b * (DDIM * 1024) + hw0;
    const float* ebase = g_eT + ct * BN;

    const int tx = tid & 15;            // 8-code group
    const int ty = tid >> 4;            // 8-row group

    issue_tiles(As0, Bs0, xbase, ebase, 0, tid);

    unsigned long long acc[4][8];       // [row-pair][code] packed fp32x2
    #pragma unroll
    for (int i = 0; i < 4; i++)
        #pragma unroll
        for (int j = 0; j < 8; j++) acc[i][j] = 0ULL;

    for (int c = 0; c < 8; c++) {
        const float* Ab = (c & 1) ? As1 : As0;
        const float* Bb = (c & 1) ? Bs1 : Bs0;
        if (c < 7) {
            issue_tiles(((c + 1) & 1) ? As1 : As0, ((c + 1) & 1) ? Bs1 : Bs0,
                        xbase, ebase, (c + 1) * BK, tid);
            asm volatile("cp.async.wait_group 1;");
        } else {
            asm volatile("cp.async.wait_group 0;");
        }
        __syncthreads();

        #pragma unroll 8
        for (int k = 0; k < BK; k++) {
            unsigned long long aP[4];
            #pragma unroll
            for (int i = 0; i < 4; i++)
                aP[i] = *reinterpret_cast<const unsigned long long*>(
                    Ab + k * BM + ty * 8 + i * 2);
            float4 b0 = *reinterpret_cast<const float4*>(Bb + k * BN + tx * 8);
            float4 b1 = *reinterpret_cast<const float4*>(Bb + k * BN + tx * 8 + 4);
            unsigned long long bd[8];
            bd[0] = dup2(b0.x); bd[1] = dup2(b0.y); bd[2] = dup2(b0.z); bd[3] = dup2(b0.w);
            bd[4] = dup2(b1.x); bd[5] = dup2(b1.y); bd[6] = dup2(b1.z); bd[7] = dup2(b1.w);
            #pragma unroll
            for (int i = 0; i < 4; i++)
                #pragma unroll
                for (int j = 0; j < 8; j++)
                    fma2(acc[i][j], aP[i], bd[j]);
        }
        __syncthreads();
    }

    // ---- epilogue: score -> per-row argmin over this block's 128 codes ----
    const int codeBase = ct * BN + tx * 8;
    float en[8];
    #pragma unroll
    for (int j = 0; j < 8; j++) en[j] = enorm[codeBase + j];

    #pragma unroll
    for (int i = 0; i < 4; i++) {
        unsigned long long bestLo = 0xFFFFFFFFFFFFFFFFull;
        unsigned long long bestHi = 0xFFFFFFFFFFFFFFFFull;
        #pragma unroll
        for (int j = 0; j < 8; j++) {
            float dLo, dHi;
            unpack2(acc[i][j], dLo, dHi);
            unsigned long long kLo = pack_key(en[j] - 2.0f * dLo, codeBase + j);
            unsigned long long kHi = pack_key(en[j] - 2.0f * dHi, codeBase + j);
            bestLo = (kLo < bestLo) ? kLo : bestLo;
            bestHi = (kHi < bestHi) ? kHi : bestHi;
        }
        // reduce across the 16 tx lanes (same half-warp: lane = ty%2*16 + tx)
        #pragma unroll
        for (int off = 1; off < 16; off <<= 1) {
            unsigned long long o = __shfl_xor_sync(0xFFFFFFFFu, bestLo, off);
            bestLo = (o < bestLo) ? o : bestLo;
            o = __shfl_xor_sync(0xFFFFFFFFu, bestHi, off);
            bestHi = (o < bestHi) ? o : bestHi;
        }
        if (tx == 0) {
            int r0 = m0 + ty * 8 + i * 2;
            atomicMin(rowmin + r0,     bestLo);   // no return use -> REDG.MIN
            atomicMin(rowmin + r0 + 1, bestHi);
        }
    }
}

// ---------------- extract argmin index from packed keys ----------------
__global__ void extract_kernel(const unsigned long long* __restrict__ rm,
                               int* __restrict__ idx) {
    int n = blockIdx.x * 256 + threadIdx.x;
    if (n < NROWS) idx[n] = (int)(rm[n] & 0xFFFFFFFFu);
}

// ---------------- gather quantized + commitment-loss accumulation ----------------
// outq = d_out + 1 is only 4B aligned -> scalar stores.
__global__ void gather_loss_kernel(const float* __restrict__ x,
                                   const float* __restrict__ emb,
                                   const int* __restrict__ idx,
                                   float* __restrict__ outq) {
    const int t = blockIdx.x * blockDim.x + threadIdx.x;
    double local = 0.0;
    for (int v = t; v < Q_ELEMS / 4; v += 524288) {
        int i  = v * 4;
        int hw = i & 1023;
        int c  = (i >> 10) & 255;
        int b  = i >> 18;
        int n0 = (b << 10) | hw;
        float4 xv = *reinterpret_cast<const float4*>(x + i);
        int id0 = idx[n0], id1 = idx[n0 + 1], id2 = idx[n0 + 2], id3 = idx[n0 + 3];
        float q0 = emb[id0 * DDIM + c];
        float q1 = emb[id1 * DDIM + c];
        float q2 = emb[id2 * DDIM + c];
        float q3 = emb[id3 * DDIM + c];
        outq[i + 0] = xv.x + (q0 - xv.x);
        outq[i + 1] = xv.y + (q1 - xv.y);
        outq[i + 2] = xv.z + (q2 - xv.z);
        outq[i + 3] = xv.w + (q3 - xv.w);
        float d0 = q0 - xv.x, d1 = q1 - xv.y, d2 = q2 - xv.z, d3 = q3 - xv.w;
        local += (double)(d0 * d0 + d1 * d1) + (double)(d2 * d2 + d3 * d3);
    }
    __shared__ double red[256];
    red[threadIdx.x] = local;
    __syncthreads();
    for (int s = 128; s > 0; s >>= 1) {
        if (threadIdx.x < s) red[threadIdx.x] += red[threadIdx.x + s];
        __syncthreads();
    }
    if (threadIdx.x == 0) atomicAdd(&g_loss, red[0]);
}

// ---------------- one-hot encodings + histogram ----------------
__global__ void onehot_kernel(const int* __restrict__ idx, float* __restrict__ enc) {
    int n = blockIdx.x * blockDim.x + threadIdx.x;
    if (n < NROWS) {
        int id = idx[n];
        enc[(size_t)n * KCODES + id] = 1.0f;
        atomicAdd(&g_counts[id], 1);
    }
}

// ---------------- finalize: loss + perplexity ----------------
__global__ void finalize_kernel(float* __restrict__ out) {
    __shared__ double red[KCODES];
    int k = threadIdx.x;
    double p = (double)g_counts[k] / (double)NROWS;
    red[k] = p * log(p + 1e-10);
    __syncthreads();
    for (int s = 512; s > 0; s >>= 1) {
        if (k < s) red[k] += red[k + s];
        __syncthreads();
    }
    if (k == 0) {
        out[PERP_OFF] = (float)exp(-red[0]);
        out[0]        = (float)(0.25 * g_loss / (double)Q_ELEMS);
    }
}

// ---------------- launch ----------------
extern "C" void kernel_launch(void* const* d_in, const int* in_sizes, int n_in,
                              void* d_out, int out_size) {
    const float* x   = (const float*)d_in[0];   // [32,256,32,32]
    const float* emb = (const float*)d_in[1];   // [1024,256]
    float* out = (float*)d_out;

    static const size_t SMEM = 2 * (BK * BM + BK * BN) * sizeof(float); // 64 KB
    cudaFuncSetAttribute(argmin_kernel,
                         cudaFuncAttributeMaxDynamicSharedMemorySize, (int)SMEM);

    // resolve ALL device-global addresses via the runtime (never pass a
    // __device__ symbol directly from host code — on GB300/ATS it silently
    // dereferences the zero-filled host shadow).
    int*                d_idx;    cudaGetSymbolAddress((void**)&d_idx,    g_idx);
    float*              d_enorm;  cudaGetSymbolAddress((void**)&d_enorm,  g_enorm);
    unsigned long long* d_rowmin; cudaGetSymbolAddress((void**)&d_rowmin, g_rowmin);

    init_kernel<<<1, 1024>>>();
    prep_kernel<<<KCODES, DDIM>>>(emb);
    cudaMemsetAsync(d_rowmin, 0xFF, (size_t)NROWS * sizeof(unsigned long long));
    cudaMemsetAsync(out + ENC_OFF, 0, (size_t)ENC_ELEMS * sizeof(float));

    argmin_kernel<<<(NROWS / BM) * (KCODES / BN), 256, SMEM>>>(x, d_enorm, d_rowmin);
    extract_kernel<<<NROWS / 256, 256>>>(d_rowmin, d_idx);

    gather_loss_kernel<<<2048, 256>>>(x, emb, d_idx, out + Q_OFF);
    onehot_kernel<<<NROWS / 256, 256>>>(d_idx, out + ENC_OFF);
    finalize_kernel<<<1, KCODES>>>(out);
}

// round 9
// speedup vs baseline: 1.0043x; 1.0041x over previous
#include <cuda_runtime.h>
#include <math.h>
#include <stdint.h>

// ---------------- problem constants ----------------
#define NROWS   32768          // 32 * 32 * 32  (B * H * W)
#define DDIM    256            // channels / code dim
#define KCODES  1024           // codebook size
#define Q_ELEMS 8388608        // 32*256*32*32
#define ENC_ELEMS 33554432     // 32768 * 1024

// output layout: [loss(1) | quantized_st(Q_ELEMS) | perplexity(1) | encodings(ENC_ELEMS)]
#define Q_OFF    1
#define PERP_OFF (1 + Q_ELEMS)
#define ENC_OFF  (2 + Q_ELEMS)

// GEMM tiling
#define BM 128
#define BN 128
#define BK 32

// ---------------- scratch (device globals: no allocation allowed) ----------------
__device__ float              g_eT[DDIM * KCODES];   // embedding transposed [d][k]
__device__ float              g_enorm[KCODES];       // ||e_k||^2
__device__ unsigned long long g_rowmin[NROWS];       // packed (score|code) per row
__device__ int                g_idx[NROWS];          // argmin index per row
__device__ int                g_counts[KCODES];      // histogram
__device__ double             g_loss;                // sum of squared diffs

// ---------------- packed f32x2 helpers ----------------
__device__ __forceinline__ unsigned long long dup2(float v) {
    unsigned long long r;
    asm("mov.b64 %0, {%1, %1};" : "=l"(r) : "r"(__float_as_uint(v)));
    return r;
}
__device__ __forceinline__ void unpack2(unsigned long long p, float& lo, float& hi) {
    unsigned int a, b;
    asm("mov.b64 {%0, %1}, %2;" : "=r"(a), "=r"(b) : "l"(p));
    lo = __uint_as_float(a);
    hi = __uint_as_float(b);
}
__device__ __forceinline__ void fma2(unsigned long long& acc,
                                     unsigned long long a, unsigned long long b) {
    asm("fma.rn.f32x2 %0, %1, %2, %0;" : "+l"(acc) : "l"(a), "l"(b));
}

// ---------------- init: zero accumulators ----------------
__global__ void init_kernel() {
    int t = threadIdx.x;
    if (t < KCODES) g_counts[t] = 0;
    if (t == 0) g_loss = 0.0;
}

// ---------------- prep: transpose embedding + norms (exact fp32) ----------------
__global__ void prep_kernel(const float* __restrict__ emb) {
    int k = blockIdx.x;
    int d = threadIdx.x;
    float v = emb[k * DDIM + d];
    g_eT[d * KCODES + k] = v;
    __shared__ float red[DDIM];
    red[d] = v * v;
    __syncthreads();
    for (int s = 128; s > 0; s >>= 1) {
        if (d < s) red[d] += red[d + s];
        __syncthreads();
    }
    if (d == 0) g_enorm[k] = red[0];
}

// ---------------- argmin key packing (ties -> lowest index, like jnp.argmin) ----------------
__device__ __forceinline__ unsigned long long pack_key(float s, int code) {
    unsigned int u = __float_as_uint(s);
    u = (u & 0x80000000u) ? ~u : (u | 0x80000000u);
    return (((unsigned long long)u) << 32) | (unsigned int)code;
}

// ---------------- cp.async tile loader ----------------
__device__ __forceinline__ void issue_tiles(float* As, float* Bs,
                                            const float* xbase, const float* ebase,
                                            int kk, int tid) {
    #pragma unroll
    for (int i = 0; i < 4; i++) {
        int t  = tid + i * 256;              // 0..1023 float4 slots
        int k  = t >> 5;
        int m4 = t & 31;
        const float* src = xbase + (size_t)(kk + k) * 1024 + m4 * 4;
        unsigned int dst = (unsigned int)__cvta_generic_to_shared(As + k * BM + m4 * 4);
        asm volatile("cp.async.cg.shared.global [%0], [%1], 16;" :: "r"(dst), "l"(src));
    }
    #pragma unroll
    for (int i = 0; i < 4; i++) {
        int t  = tid + i * 256;
        int k  = t >> 5;
        int n4 = t & 31;
        const float* src = ebase + (size_t)(kk + k) * KCODES + n4 * 4;
        unsigned int dst = (unsigned int)__cvta_generic_to_shared(Bs + k * BN + n4 * 4);
        asm volatile("cp.async.cg.shared.global [%0], [%1], 16;" :: "r"(dst), "l"(src));
    }
    asm volatile("cp.async.commit_group;");
}

// ---------------- main: fused fp32 GEMM (FFMA2) + argmin ----------------
// grid = 2048 blocks: rowTile = bx>>3 (128 rows), codeTile = bx&7 (128 codes, fast idx
// so the 8 blocks sharing an A tile run concurrently and hit L2).
// score_k = ||e_k||^2 - 2 * x.e_k  (||x||^2 per-row constant -> argmin-invariant)
__global__ __launch_bounds__(256, 2)
void argmin_kernel(const float* __restrict__ x,
                   const float* __restrict__ enorm,
                   unsigned long long* __restrict__ rowmin) {
    extern __shared__ float sm[];
    float* As0 = sm;                    // [BK][BM]
    float* As1 = sm + BK * BM;
    float* Bs0 = sm + 2 * BK * BM;      // [BK][BN]
    float* Bs1 = sm + 2 * BK * BM + BK * BN;

    const int tid = threadIdx.x;
    const int bx  = blockIdx.x;
    const int rowTile = bx >> 3;
    const int ct      = bx & 7;
    const int m0  = rowTile * BM;       // global row base (128 rows, same batch b)
    const int b   = m0 >> 10;
    const int hw0 = m0 & 1023;
    const float* xbase = x + (size_t)b * (DDIM * 1024) + hw0;
    const float* ebase = g_eT + ct * BN;

    const int tx = tid & 15;            // 8-code group
    const int ty = tid >> 4;            // 8-row group

    issue_tiles(As0, Bs0, xbase, ebase, 0, tid);

    unsigned long long acc[4][8];       // [row-pair][code] packed fp32x2
    #pragma unroll
    for (int i = 0; i < 4; i++)
        #pragma unroll
        for (int j = 0; j < 8; j++) acc[i][j] = 0ULL;

    for (int c = 0; c < 8; c++) {
        const float* Ab = (c & 1) ? As1 : As0;
        const float* Bb = (c & 1) ? Bs1 : Bs0;
        if (c < 7) {
            issue_tiles(((c + 1) & 1) ? As1 : As0, ((c + 1) & 1) ? Bs1 : Bs0,
                        xbase, ebase, (c + 1) * BK, tid);
            asm volatile("cp.async.wait_group 1;");
        } else {
            asm volatile("cp.async.wait_group 0;");
        }
        __syncthreads();

        #pragma unroll 8
        for (int k = 0; k < BK; k++) {
            unsigned long long aP[4];
            #pragma unroll
            for (int i = 0; i < 4; i++)
                aP[i] = *reinterpret_cast<const unsigned long long*>(
                    Ab + k * BM + ty * 8 + i * 2);
            float4 b0 = *reinterpret_cast<const float4*>(Bb + k * BN + tx * 8);
            float4 b1 = *reinterpret_cast<const float4*>(Bb + k * BN + tx * 8 + 4);
            unsigned long long bd[8];
            bd[0] = dup2(b0.x); bd[1] = dup2(b0.y); bd[2] = dup2(b0.z); bd[3] = dup2(b0.w);
            bd[4] = dup2(b1.x); bd[5] = dup2(b1.y); bd[6] = dup2(b1.z); bd[7] = dup2(b1.w);
            #pragma unroll
            for (int i = 0; i < 4; i++)
                #pragma unroll
                for (int j = 0; j < 8; j++)
                    fma2(acc[i][j], aP[i], bd[j]);
        }
        __syncthreads();
    }

    // ---- epilogue: score -> per-row argmin over this block's 128 codes ----
    const int codeBase = ct * BN + tx * 8;
    float en[8];
    #pragma unroll
    for (int j = 0; j < 8; j++) en[j] = enorm[codeBase + j];

    #pragma unroll
    for (int i = 0; i < 4; i++) {
        unsigned long long bestLo = 0xFFFFFFFFFFFFFFFFull;
        unsigned long long bestHi = 0xFFFFFFFFFFFFFFFFull;
        #pragma unroll
        for (int j = 0; j < 8; j++) {
            float dLo, dHi;
            unpack2(acc[i][j], dLo, dHi);
            unsigned long long kLo = pack_key(en[j] - 2.0f * dLo, codeBase + j);
            unsigned long long kHi = pack_key(en[j] - 2.0f * dHi, codeBase + j);
            bestLo = (kLo < bestLo) ? kLo : bestLo;
            bestHi = (kHi < bestHi) ? kHi : bestHi;
        }
        // reduce across the 16 tx lanes (same half-warp: lane = ty%2*16 + tx)
        #pragma unroll
        for (int off = 1; off < 16; off <<= 1) {
            unsigned long long o = __shfl_xor_sync(0xFFFFFFFFu, bestLo, off);
            bestLo = (o < bestLo) ? o : bestLo;
            o = __shfl_xor_sync(0xFFFFFFFFu, bestHi, off);
            bestHi = (o < bestHi) ? o : bestHi;
        }
        if (tx == 0) {
            int r0 = m0 + ty * 8 + i * 2;
            atomicMin(rowmin + r0,     bestLo);   // no return use -> REDG.MIN
            atomicMin(rowmin + r0 + 1, bestHi);
        }
    }
}

// ---------------- extract argmin index from packed keys ----------------
__global__ void extract_kernel(const unsigned long long* __restrict__ rm,
                               int* __restrict__ idx) {
    int n = blockIdx.x * 256 + threadIdx.x;
    if (n < NROWS) idx[n] = (int)(rm[n] & 0xFFFFFFFFu);
}

// ---------------- gather quantized + commitment-loss accumulation ----------------
// outq = d_out + 1 is only 4B aligned -> scalar stores.
__global__ void gather_loss_kernel(const float* __restrict__ x,
                                   const float* __restrict__ emb,
                                   const int* __restrict__ idx,
                                   float* __restrict__ outq) {
    const int t = blockIdx.x * blockDim.x + threadIdx.x;
    double local = 0.0;
    for (int v = t; v < Q_ELEMS / 4; v += 524288) {
        int i  = v * 4;
        int hw = i & 1023;
        int c  = (i >> 10) & 255;
        int b  = i >> 18;
        int n0 = (b << 10) | hw;
        float4 xv = *reinterpret_cast<const float4*>(x + i);
        int id0 = idx[n0], id1 = idx[n0 + 1], id2 = idx[n0 + 2], id3 = idx[n0 + 3];
        float q0 = emb[id0 * DDIM + c];
        float q1 = emb[id1 * DDIM + c];
        float q2 = emb[id2 * DDIM + c];
        float q3 = emb[id3 * DDIM + c];
        outq[i + 0] = xv.x + (q0 - xv.x);
        outq[i + 1] = xv.y + (q1 - xv.y);
        outq[i + 2] = xv.z + (q2 - xv.z);
        outq[i + 3] = xv.w + (q3 - xv.w);
        float d0 = q0 - xv.x, d1 = q1 - xv.y, d2 = q2 - xv.z, d3 = q3 - xv.w;
        local += (double)(d0 * d0 + d1 * d1) + (double)(d2 * d2 + d3 * d3);
    }
    __shared__ double red[256];
    red[threadIdx.x] = local;
    __syncthreads();
    for (int s = 128; s > 0; s >>= 1) {
        if (threadIdx.x < s) red[threadIdx.x] += red[threadIdx.x + s];
        __syncthreads();
    }
    if (threadIdx.x == 0) atomicAdd(&g_loss, red[0]);
}

// ---------------- one-hot encodings + histogram ----------------
__global__ void onehot_kernel(const int* __restrict__ idx, float* __restrict__ enc) {
    int n = blockIdx.x * blockDim.x + threadIdx.x;
    if (n < NROWS) {
        int id = idx[n];
        enc[(size_t)n * KCODES + id] = 1.0f;
        atomicAdd(&g_counts[id], 1);
    }
}

// ---------------- finalize: loss + perplexity ----------------
__global__ void finalize_kernel(float* __restrict__ out) {
    __shared__ double red[KCODES];
    int k = threadIdx.x;
    double p = (double)g_counts[k] / (double)NROWS;
    red[k] = p * log(p + 1e-10);
    __syncthreads();
    for (int s = 512; s > 0; s >>= 1) {
        if (k < s) red[k] += red[k + s];
        __syncthreads();
    }
    if (k == 0) {
        out[PERP_OFF] = (float)exp(-red[0]);
        out[0]        = (float)(0.25 * g_loss / (double)Q_ELEMS);
    }
}

// ---------------- launch ----------------
extern "C" void kernel_launch(void* const* d_in, const int* in_sizes, int n_in,
                              void* d_out, int out_size) {
    const float* x   = (const float*)d_in[0];   // [32,256,32,32]
    const float* emb = (const float*)d_in[1];   // [1024,256]
    float* out = (float*)d_out;

    static const size_t SMEM = 2 * (BK * BM + BK * BN) * sizeof(float); // 64 KB
    cudaFuncSetAttribute(argmin_kernel,
                         cudaFuncAttributeMaxDynamicSharedMemorySize, (int)SMEM);

    // resolve ALL device-global addresses via the runtime (never pass a
    // __device__ symbol directly from host code — on GB300/ATS it silently
    // dereferences the zero-filled host shadow).
    int*                d_idx;    cudaGetSymbolAddress((void**)&d_idx,    g_idx);
    float*              d_enorm;  cudaGetSymbolAddress((void**)&d_enorm,  g_enorm);
    unsigned long long* d_rowmin; cudaGetSymbolAddress((void**)&d_rowmin, g_rowmin);

    init_kernel<<<1, 1024>>>();
    prep_kernel<<<KCODES, DDIM>>>(emb);
    cudaMemsetAsync(d_rowmin, 0xFF, (size_t)NROWS * sizeof(unsigned long long));
    cudaMemsetAsync(out + ENC_OFF, 0, (size_t)ENC_ELEMS * sizeof(float));

    argmin_kernel<<<(NROWS / BM) * (KCODES / BN), 256, SMEM>>>(x, d_enorm, d_rowmin);
    extract_kernel<<<NROWS / 256, 256>>>(d_rowmin, d_idx);

    gather_loss_kernel<<<2048, 256>>>(x, emb, d_idx, out + Q_OFF);
    onehot_kernel<<<NROWS / 256, 256>>>(d_idx, out + ENC_OFF);
    finalize_kernel<<<1, KCODES>>>(out);
}